// round 2
// baseline (speedup 1.0000x reference)
#include <cuda_runtime.h>

#define BB 2
#define TT 5
#define NNq 4096
#define CC 16
#define DD 128
#define NSrc 16384          // (T-1)*N
#define MM (BB*NNq)         // 8192
#define EPSV 1e-5f
#define RAD2 1.0f

// ---------------- scratch (__device__ globals; no allocation allowed) ----------------
__device__ float4 g_xyzw[BB*NSrc];                 // packed src xyz + |s|^2
__device__ float  g_hpre[(size_t)MM*DD*4];         // conv output pre-BN (m, o, s)  16MB
__device__ float  g_y0[(size_t)MM*DD];             // fc1 out (m,c)
__device__ float  g_y1[(size_t)MM*DD];             // fc2 out
__device__ float  g_y2[(size_t)MM*DD];             // fc3 out
#define CPART 64
__device__ float  g_cs[CPART][DD];
__device__ float  g_cq[CPART][DD];
__device__ float  g_scale[DD];
__device__ float  g_shift[DD];
#define YPART 32
__device__ float  g_ys[3][YPART][DD];
__device__ float  g_yq[3][YPART][DD];
__device__ float  g_yscale[3][DD];
__device__ float  g_yshift[3][DD];

// ---------------- K1: pack source xyz + sumsq ----------------
__global__ void k_pack(const float* __restrict__ x) {
    int i = blockIdx.x * blockDim.x + threadIdx.x;
    if (i >= BB*NSrc) return;
    int b = i / NSrc, j = i % NSrc;
    int t = 1 + j / NNq, n = j % NNq;
    const float* p = x + (((size_t)b*TT + t)*NNq + n)*CC;
    float px = p[0], py = p[1], pz = p[2];
    g_xyzw[i] = make_float4(px, py, pz, px*px + py*py + pz*pz);
}

// ---------------- K2: ball query (first 4 hits, early exit) + conv ----------------
__global__ void k_ballconv(const float* __restrict__ x,
                           const float* __restrict__ w,
                           const float* __restrict__ bias) {
    __shared__ float sg[8][64];   // per-warp grouped feats [s][c]
    int gw   = (blockIdx.x * blockDim.x + threadIdx.x) >> 5;
    int lane = threadIdx.x & 31;
    if (gw >= MM) return;
    int b = gw >> 12, q = gw & (NNq - 1);

    const float* qp = x + (((size_t)b*TT + 0)*NNq + q)*CC;
    float qx = qp[0], qy = qp[1], qz = qp[2];
    float qq = qx*qx + qy*qy + qz*qz;

    const float4* src = g_xyzw + (size_t)b*NSrc;
    int i0 = 0, i1 = 0, i2 = 0, i3 = 0, cnt = 0;
    for (int chunk = 0; chunk < NSrc/32 && cnt < 4; chunk++) {
        float4 p = src[chunk*32 + lane];
        float dot = fmaf(qx, p.x, fmaf(qy, p.y, qz*p.z));
        float d2  = fmaf(-2.0f, dot, qq + p.w);
        unsigned mask = __ballot_sync(0xffffffffu, d2 < RAD2);
        while (mask && cnt < 4) {
            int id = chunk*32 + (__ffs(mask) - 1);
            if      (cnt == 0) i0 = id;
            else if (cnt == 1) i1 = id;
            else if (cnt == 2) i2 = id;
            else               i3 = id;
            cnt++;
            mask &= mask - 1;
        }
    }
    bool empty = (cnt == 0);
    if (cnt < 2) i1 = i0;
    if (cnt < 3) i2 = i0;
    if (cnt < 4) i3 = i0;

    // gather grouped feats into shared  (g[s][c])
    float* gg = &sg[threadIdx.x >> 5][0];
    const float* feats = x + ((size_t)b*TT + 1)*NNq*CC;
    #pragma unroll
    for (int r = 0; r < 2; r++) {
        int v = lane + r*32;          // v = s*16 + c
        int s = v >> 4, c = v & 15;
        int id = (s == 0) ? i0 : (s == 1) ? i1 : (s == 2) ? i2 : i3;
        gg[v] = empty ? 0.0f : feats[(size_t)id*CC + c];
    }
    __syncwarp();

    // conv: h[m,o,s] = sum_c g[s][c]*w[o,c] + b[o]
    float* hout = g_hpre + (size_t)gw * (DD*4);
    #pragma unroll
    for (int j = 0; j < 4; j++) {
        int o = lane + j*32;
        float bo = bias[o];
        float a0 = bo, a1 = bo, a2 = bo, a3 = bo;
        const float* wr = w + o*CC;
        #pragma unroll
        for (int c = 0; c < CC; c++) {
            float wv = wr[c];
            a0 = fmaf(wv, gg[0*16 + c], a0);
            a1 = fmaf(wv, gg[1*16 + c], a1);
            a2 = fmaf(wv, gg[2*16 + c], a2);
            a3 = fmaf(wv, gg[3*16 + c], a3);
        }
        *(float4*)(hout + o*4) = make_float4(a0, a1, a2, a3);
    }
}

// ---------------- K3a: conv-BN partial stats (coalesced over rows) ----------------
__global__ void k_cstat() {
    int blk = blockIdx.x, c = threadIdx.x;
    const int rows = MM / CPART;
    float s = 0.f, qv = 0.f;
    for (int m = blk*rows; m < (blk+1)*rows; m++) {
        float4 v = *(const float4*)(g_hpre + (size_t)m*(DD*4) + c*4);
        s  += v.x + v.y + v.z + v.w;
        qv += v.x*v.x + v.y*v.y + v.z*v.z + v.w*v.w;
    }
    g_cs[blk][c] = s;
    g_cq[blk][c] = qv;
}

// ---------------- K3b: finalize conv-BN scale/shift ----------------
__global__ void k_cfin(const float* __restrict__ bng, const float* __restrict__ bnb) {
    int c = threadIdx.x;
    float s = 0.f, qv = 0.f;
    for (int p = 0; p < CPART; p++) { s += g_cs[p][c]; qv += g_cq[p][c]; }
    float inv = 1.0f / (float)(MM*4);
    float mean = s * inv;
    float var  = qv * inv - mean*mean;
    float sc = bng[c] * rsqrtf(var + EPSV);
    g_scale[c] = sc;
    g_shift[c] = bnb[c] - mean * sc;
}

// ---------------- K4: BN+maxpool -> feature, then fused 3x(128x128) GEMM ----------------
__global__ void __launch_bounds__(384) k_gemm(
        const float* __restrict__ fc1w, const float* __restrict__ fc1b,
        const float* __restrict__ fc2w, const float* __restrict__ fc2b,
        const float* __restrict__ fc3w, const float* __restrict__ fc3b,
        float* __restrict__ feat_out) {
    __shared__ float sh[32*DD];
    int m0 = blockIdx.x * 32;

    for (int v = threadIdx.x; v < 32*DD; v += 384) {
        int mi = v >> 7, o = v & 127;
        float4 h4 = *(const float4*)(g_hpre + (size_t)(m0+mi)*(DD*4) + o*4);
        float sc = g_scale[o], sf = g_shift[o];
        float hv = fmaf(sc, h4.x, sf);
        hv = fmaxf(hv, fmaf(sc, h4.y, sf));
        hv = fmaxf(hv, fmaf(sc, h4.z, sf));
        hv = fmaxf(hv, fmaf(sc, h4.w, sf));
        sh[v] = hv;
        feat_out[(size_t)(m0+mi)*DD + o] = hv;
    }
    __syncthreads();

    int k = threadIdx.x >> 7;
    int c = threadIdx.x & 127;
    const float* W  = (k == 0 ? fc1w : (k == 1 ? fc2w : fc3w)) + (size_t)c*DD;
    float        bb = (k == 0 ? fc1b : (k == 1 ? fc2b : fc3b))[c];
    float acc[32];
    #pragma unroll
    for (int mi = 0; mi < 32; mi++) acc[mi] = bb;
    for (int o = 0; o < DD; o += 4) {
        float4 w4 = *(const float4*)(W + o);
        #pragma unroll
        for (int mi = 0; mi < 32; mi++) {
            float4 h4 = *(const float4*)(&sh[mi*DD + o]);
            acc[mi] = fmaf(w4.x, h4.x, fmaf(w4.y, h4.y,
                      fmaf(w4.z, h4.z, fmaf(w4.w, h4.w, acc[mi]))));
        }
    }
    float* yk = (k == 0) ? g_y0 : (k == 1) ? g_y1 : g_y2;
    #pragma unroll
    for (int mi = 0; mi < 32; mi++)
        yk[(size_t)(m0+mi)*DD + c] = acc[mi];
}

// ---------------- K5a: y-BN partial stats ----------------
__global__ void k_ystat() {
    int k = blockIdx.x / YPART, p = blockIdx.x % YPART;
    int c = threadIdx.x;
    const float* Y = (k == 0) ? g_y0 : (k == 1) ? g_y1 : g_y2;
    const int rows = MM / YPART;
    float s = 0.f, qv = 0.f;
    for (int m = p*rows; m < (p+1)*rows; m++) {
        float v = Y[(size_t)m*DD + c];
        s += v; qv += v*v;
    }
    g_ys[k][p][c] = s;
    g_yq[k][p][c] = qv;
}

// ---------------- K5b: finalize y-BN ----------------
__global__ void k_yfin(const float* __restrict__ bng, const float* __restrict__ bnb) {
    int k = threadIdx.x >> 7, c = threadIdx.x & 127;
    float s = 0.f, qv = 0.f;
    for (int p = 0; p < YPART; p++) { s += g_ys[k][p][c]; qv += g_yq[k][p][c]; }
    float inv = 1.0f / (float)MM;
    float mean = s * inv;
    float var  = qv * inv - mean*mean;
    float sc = bng[c] * rsqrtf(var + EPSV);
    g_yscale[k][c] = sc;
    g_yshift[k][c] = bnb[c] - mean * sc;
}

// ---------------- K7: relu(BN(y)) -> 7 head outputs, warp per m ----------------
__global__ void k_out(const float* __restrict__ cew, const float* __restrict__ ceb,
                      const float* __restrict__ lww, const float* __restrict__ lwb,
                      const float* __restrict__ thw, const float* __restrict__ thb,
                      float* __restrict__ out) {
    int gw   = (blockIdx.x * blockDim.x + threadIdx.x) >> 5;
    int lane = threadIdx.x & 31;
    if (gw >= MM) return;
    int o = lane * 4;
    float r0, r1, r2, r3, r4, r5, r6;
    {
        float4 y = *(const float4*)(g_y0 + (size_t)gw*DD + o);
        float x0 = fmaxf(0.f, fmaf(g_yscale[0][o+0], y.x, g_yshift[0][o+0]));
        float x1 = fmaxf(0.f, fmaf(g_yscale[0][o+1], y.y, g_yshift[0][o+1]));
        float x2 = fmaxf(0.f, fmaf(g_yscale[0][o+2], y.z, g_yshift[0][o+2]));
        float x3 = fmaxf(0.f, fmaf(g_yscale[0][o+3], y.w, g_yshift[0][o+3]));
        float4 w0 = *(const float4*)(cew + 0*DD + o);
        float4 w1 = *(const float4*)(cew + 1*DD + o);
        float4 w2 = *(const float4*)(cew + 2*DD + o);
        r0 = x0*w0.x + x1*w0.y + x2*w0.z + x3*w0.w;
        r1 = x0*w1.x + x1*w1.y + x2*w1.z + x3*w1.w;
        r2 = x0*w2.x + x1*w2.y + x2*w2.z + x3*w2.w;
    }
    {
        float4 y = *(const float4*)(g_y1 + (size_t)gw*DD + o);
        float x0 = fmaxf(0.f, fmaf(g_yscale[1][o+0], y.x, g_yshift[1][o+0]));
        float x1 = fmaxf(0.f, fmaf(g_yscale[1][o+1], y.y, g_yshift[1][o+1]));
        float x2 = fmaxf(0.f, fmaf(g_yscale[1][o+2], y.z, g_yshift[1][o+2]));
        float x3 = fmaxf(0.f, fmaf(g_yscale[1][o+3], y.w, g_yshift[1][o+3]));
        float4 w0 = *(const float4*)(lww + 0*DD + o);
        float4 w1 = *(const float4*)(lww + 1*DD + o);
        float4 w2 = *(const float4*)(lww + 2*DD + o);
        r3 = x0*w0.x + x1*w0.y + x2*w0.z + x3*w0.w;
        r4 = x0*w1.x + x1*w1.y + x2*w1.z + x3*w1.w;
        r5 = x0*w2.x + x1*w2.y + x2*w2.z + x3*w2.w;
    }
    {
        float4 y = *(const float4*)(g_y2 + (size_t)gw*DD + o);
        float x0 = fmaxf(0.f, fmaf(g_yscale[2][o+0], y.x, g_yshift[2][o+0]));
        float x1 = fmaxf(0.f, fmaf(g_yscale[2][o+1], y.y, g_yshift[2][o+1]));
        float x2 = fmaxf(0.f, fmaf(g_yscale[2][o+2], y.z, g_yshift[2][o+2]));
        float x3 = fmaxf(0.f, fmaf(g_yscale[2][o+3], y.w, g_yshift[2][o+3]));
        float4 w0 = *(const float4*)(thw + o);
        r6 = x0*w0.x + x1*w0.y + x2*w0.z + x3*w0.w;
    }
    #pragma unroll
    for (int off = 16; off; off >>= 1) {
        r0 += __shfl_xor_sync(0xffffffffu, r0, off);
        r1 += __shfl_xor_sync(0xffffffffu, r1, off);
        r2 += __shfl_xor_sync(0xffffffffu, r2, off);
        r3 += __shfl_xor_sync(0xffffffffu, r3, off);
        r4 += __shfl_xor_sync(0xffffffffu, r4, off);
        r5 += __shfl_xor_sync(0xffffffffu, r5, off);
        r6 += __shfl_xor_sync(0xffffffffu, r6, off);
    }
    if (lane == 0) {
        float* op = out + (size_t)gw*7;
        op[0] = r0 + ceb[0];
        op[1] = r1 + ceb[1];
        op[2] = r2 + ceb[2];
        op[3] = r3 + lwb[0];
        op[4] = r4 + lwb[1];
        op[5] = r5 + lwb[2];
        op[6] = r6 + thb[0];
    }
}

// ---------------- launch ----------------
extern "C" void kernel_launch(void* const* d_in, const int* in_sizes, int n_in,
                              void* d_out, int out_size) {
    const float* x        = (const float*)d_in[0];
    const float* conv1_w  = (const float*)d_in[1];
    const float* conv1_b  = (const float*)d_in[2];
    const float* bn_g     = (const float*)d_in[3];
    const float* bn_b     = (const float*)d_in[4];
    const float* fc1_w    = (const float*)d_in[5];
    const float* fc1_b    = (const float*)d_in[6];
    const float* fc_ce_w  = (const float*)d_in[7];
    const float* fc_ce_b  = (const float*)d_in[8];
    const float* fc2_w    = (const float*)d_in[9];
    const float* fc2_b    = (const float*)d_in[10];
    const float* fc_lwh_w = (const float*)d_in[11];
    const float* fc_lwh_b = (const float*)d_in[12];
    const float* fc3_w    = (const float*)d_in[13];
    const float* fc3_b    = (const float*)d_in[14];
    const float* fc_th_w  = (const float*)d_in[15];
    const float* fc_th_b  = (const float*)d_in[16];

    float* out  = (float*)d_out;             // (B,N,7) flattened
    float* feat = out + (size_t)MM * 7;      // (B,N,128) flattened after it

    k_pack<<<(BB*NSrc + 255)/256, 256>>>(x);
    k_ballconv<<<MM/8, 256>>>(x, conv1_w, conv1_b);
    k_cstat<<<CPART, DD>>>();
    k_cfin<<<1, DD>>>(bn_g, bn_b);
    k_gemm<<<MM/32, 384>>>(fc1_w, fc1_b, fc2_w, fc2_b, fc3_w, fc3_b, feat);
    k_ystat<<<3*YPART, DD>>>();
    k_yfin<<<1, 3*DD>>>(bn_g, bn_b);
    k_out<<<MM/8, 256>>>(fc_ce_w, fc_ce_b, fc_lwh_w, fc_lwh_b, fc_th_w, fc_th_b, out);
}

// round 4
// speedup vs baseline: 2.0247x; 2.0247x over previous
#include <cuda_runtime.h>

#define BB 2
#define TT 5
#define NNq 4096
#define CC 16
#define DD 128
#define NSrc 16384          // (T-1)*N
#define MM (BB*NNq)         // 8192
#define EPSV 1e-5f
#define RAD2 1.0f

// ---------------- scratch (__device__ globals; no allocation allowed) ----------------
__device__ float4 g_xyzw[BB*NSrc];                 // packed src xyz + |s|^2
__device__ float  g_hpre[(size_t)MM*DD*4];         // conv output pre-BN (m, o, s)  16MB
__device__ float  g_y0[(size_t)MM*DD];             // fc1 out (m,c)
__device__ float  g_y1[(size_t)MM*DD];             // fc2 out
__device__ float  g_y2[(size_t)MM*DD];             // fc3 out
// fused BN statistic accumulators
__device__ float  g_csum[DD];
__device__ float  g_csq[DD];
__device__ float  g_ysum[3*DD];
__device__ float  g_ysq[3*DD];

// packed f32x2 fma (sm_100+)
__device__ __forceinline__ unsigned long long ffma2(unsigned long long a,
                                                    unsigned long long b,
                                                    unsigned long long c) {
    unsigned long long d;
    asm("fma.rn.f32x2 %0, %1, %2, %3;" : "=l"(d) : "l"(a), "l"(b), "l"(c));
    return d;
}
__device__ __forceinline__ unsigned long long splat2(float w) {
    unsigned long long r;
    asm("mov.b64 %0, {%1, %1};" : "=l"(r) : "r"(__float_as_uint(w)));
    return r;
}
__device__ __forceinline__ void unpack2(unsigned long long v, float& lo, float& hi) {
    unsigned a, b;
    asm("mov.b64 {%0, %1}, %2;" : "=r"(a), "=r"(b) : "l"(v));
    lo = __uint_as_float(a); hi = __uint_as_float(b);
}

// ---------------- K1: pack source xyz + sumsq, zero accumulators ----------------
__global__ void k_pack(const float* __restrict__ x) {
    int i = blockIdx.x * blockDim.x + threadIdx.x;
    if (i < DD)   { g_csum[i] = 0.f; g_csq[i] = 0.f; }
    if (i < 3*DD) { g_ysum[i] = 0.f; g_ysq[i] = 0.f; }
    if (i >= BB*NSrc) return;
    int b = i / NSrc, j = i % NSrc;
    int t = 1 + j / NNq, n = j % NNq;
    const float* p = x + (((size_t)b*TT + t)*NNq + n)*CC;
    float px = p[0], py = p[1], pz = p[2];
    g_xyzw[i] = make_float4(px, py, pz, px*px + py*py + pz*pz);
}

// ---------------- K2: ball query (first 4 hits, pipelined scan) + conv + BN stats ----
__global__ void __launch_bounds__(256) k_ballconv(const float* __restrict__ x,
                           const float* __restrict__ w,
                           const float* __restrict__ bias) {
    __shared__ float sg[8][64];   // per-warp grouped feats [s][c]
    __shared__ float ssum[DD], ssq[DD];
    int tid  = threadIdx.x;
    int gw   = (blockIdx.x * blockDim.x + tid) >> 5;
    int lane = tid & 31;
    if (tid < DD) { ssum[tid] = 0.f; ssq[tid] = 0.f; }
    __syncthreads();

    int b = gw >> 12, q = gw & (NNq - 1);

    const float* qp = x + (((size_t)b*TT + 0)*NNq + q)*CC;
    float qx = qp[0], qy = qp[1], qz = qp[2];
    float qq = qx*qx + qy*qy + qz*qz;

    const float4* src = g_xyzw + (size_t)b*NSrc;
    int i0 = 0, i1 = 0, i2 = 0, i3 = 0, cnt = 0;

    // pipelined scan: 256 points per super-chunk (8 x float4 per lane), prefetch next
    const int NCH = NSrc / 256;   // 64
    float4 P[8];
    #pragma unroll
    for (int j = 0; j < 8; j++) P[j] = src[j*32 + lane];
    for (int sc = 0; sc < NCH && cnt < 4; sc++) {
        float4 C[8];
        #pragma unroll
        for (int j = 0; j < 8; j++) C[j] = P[j];
        int nxt = (sc + 1 < NCH) ? sc + 1 : sc;
        #pragma unroll
        for (int j = 0; j < 8; j++) P[j] = src[nxt*256 + j*32 + lane];
        #pragma unroll
        for (int j = 0; j < 8; j++) {
            float dot = fmaf(qx, C[j].x, fmaf(qy, C[j].y, qz*C[j].z));
            float d2  = fmaf(-2.0f, dot, qq + C[j].w);
            unsigned mask = __ballot_sync(0xffffffffu, d2 < RAD2);
            while (mask && cnt < 4) {
                int id = sc*256 + j*32 + (__ffs(mask) - 1);
                if      (cnt == 0) i0 = id;
                else if (cnt == 1) i1 = id;
                else if (cnt == 2) i2 = id;
                else               i3 = id;
                cnt++;
                mask &= mask - 1;
            }
        }
    }
    bool empty = (cnt == 0);
    if (cnt < 2) i1 = i0;
    if (cnt < 3) i2 = i0;
    if (cnt < 4) i3 = i0;

    // gather grouped feats into shared  (g[s][c])
    float* gg = &sg[tid >> 5][0];
    const float* feats = x + ((size_t)b*TT + 1)*NNq*CC;
    #pragma unroll
    for (int r = 0; r < 2; r++) {
        int v = lane + r*32;          // v = s*16 + c
        int s = v >> 4, c = v & 15;
        int id = (s == 0) ? i0 : (s == 1) ? i1 : (s == 2) ? i2 : i3;
        gg[v] = empty ? 0.0f : feats[(size_t)id*CC + c];
    }
    __syncwarp();

    // conv: h[m,o,s] = sum_c g[s][c]*w[o,c] + b[o]; accumulate BN partials
    float* hout = g_hpre + (size_t)gw * (DD*4);
    #pragma unroll
    for (int j = 0; j < 4; j++) {
        int o = lane + j*32;
        float bo = bias[o];
        float a0 = bo, a1 = bo, a2 = bo, a3 = bo;
        const float* wr = w + o*CC;
        #pragma unroll
        for (int c = 0; c < CC; c++) {
            float wv = wr[c];
            a0 = fmaf(wv, gg[0*16 + c], a0);
            a1 = fmaf(wv, gg[1*16 + c], a1);
            a2 = fmaf(wv, gg[2*16 + c], a2);
            a3 = fmaf(wv, gg[3*16 + c], a3);
        }
        *(float4*)(hout + o*4) = make_float4(a0, a1, a2, a3);
        float s = a0 + a1 + a2 + a3;
        float qv = a0*a0 + a1*a1 + a2*a2 + a3*a3;
        atomicAdd(&ssum[o], s);
        atomicAdd(&ssq[o], qv);
    }
    __syncthreads();
    if (tid < DD) {
        atomicAdd(&g_csum[tid], ssum[tid]);
        atomicAdd(&g_csq[tid],  ssq[tid]);
    }
}

// ---------------- K3: scale compute + BN+maxpool + staged fused GEMM + y-stats -------
// dynamic smem layout (floats):
//   [0,128)            sscale
//   [128,256)          sshift
//   [256, 256+128*34)  sh transposed: sh[o*34 + mi], o=0..127, mi=0..31
//   [+..]              sw: sw[(k*128+c)*36 + oi], 3*128*36
#define SH_OFF 256
#define SH_PITCH 34
#define SW_OFF (SH_OFF + DD*SH_PITCH)
#define SW_PITCH 36
#define SMEM_FLOATS (SW_OFF + 3*DD*SW_PITCH)

__global__ void __launch_bounds__(384) k_gemm(
        const float* __restrict__ fc1w, const float* __restrict__ fc1b,
        const float* __restrict__ fc2w, const float* __restrict__ fc2b,
        const float* __restrict__ fc3w, const float* __restrict__ fc3b,
        const float* __restrict__ bng,  const float* __restrict__ bnb,
        float* __restrict__ feat_out) {
    extern __shared__ float sm[];
    float* sscale = sm;
    float* sshift = sm + DD;
    float* sh     = sm + SH_OFF;
    float* sw     = sm + SW_OFF;
    int tid = threadIdx.x;
    int m0 = blockIdx.x * 32;

    // conv-BN scale/shift from global accumulators
    if (tid < DD) {
        float inv = 1.0f / (float)(MM*4);
        float mean = g_csum[tid] * inv;
        float var  = g_csq[tid] * inv - mean*mean;
        float sc = bng[tid] * rsqrtf(var + EPSV);
        sscale[tid] = sc;
        sshift[tid] = bnb[tid] - mean * sc;
    }
    __syncthreads();

    // BN + maxpool -> sh (transposed [o][mi]) + feature output
    for (int v = tid; v < 32*DD; v += 384) {
        int mi = v >> 7, o = v & 127;
        float4 h4 = *(const float4*)(g_hpre + (size_t)(m0+mi)*(DD*4) + o*4);
        float sc = sscale[o], sf = sshift[o];
        float hv = fmaf(sc, h4.x, sf);
        hv = fmaxf(hv, fmaf(sc, h4.y, sf));
        hv = fmaxf(hv, fmaf(sc, h4.z, sf));
        hv = fmaxf(hv, fmaf(sc, h4.w, sf));
        sh[o*SH_PITCH + mi] = hv;
        feat_out[(size_t)(m0+mi)*DD + o] = hv;
    }

    int k = tid >> 7;
    int c = tid & 127;
    const float* Wg = (k == 0) ? fc1w : (k == 1) ? fc2w : fc3w;
    float        bb = ((k == 0) ? fc1b : (k == 1) ? fc2b : fc3b)[c];
    unsigned long long acc[16];
    unsigned long long b2 = splat2(bb);
    #pragma unroll
    for (int mj = 0; mj < 16; mj++) acc[mj] = b2;

    for (int oc = 0; oc < 4; oc++) {
        __syncthreads();
        // stage W chunk [3][128][32] coalesced
        for (int v = tid; v < 3*DD*32; v += 384) {
            int kk = v >> 12, rest = v & 4095;
            int cc = rest >> 5, oi = rest & 31;
            const float* Ws = (kk == 0) ? fc1w : (kk == 1) ? fc2w : fc3w;
            sw[(kk*DD + cc)*SW_PITCH + oi] = Ws[(size_t)cc*DD + oc*32 + oi];
        }
        __syncthreads();
        const float* wr = &sw[(k*DD + c)*SW_PITCH];
        #pragma unroll
        for (int oi = 0; oi < 32; oi += 4) {
            float4 w4 = *(const float4*)(wr + oi);
            #pragma unroll
            for (int u = 0; u < 4; u++) {
                float wv = (u == 0) ? w4.x : (u == 1) ? w4.y : (u == 2) ? w4.z : w4.w;
                unsigned long long w2 = splat2(wv);
                int o = oc*32 + oi + u;
                const unsigned long long* hb =
                    reinterpret_cast<const unsigned long long*>(&sh[o*SH_PITCH]);
                #pragma unroll
                for (int mj = 0; mj < 16; mj++)
                    acc[mj] = ffma2(w2, hb[mj], acc[mj]);
            }
        }
    }
    (void)Wg;

    float* yk = (k == 0) ? g_y0 : (k == 1) ? g_y1 : g_y2;
    float s = 0.f, qv = 0.f;
    #pragma unroll
    for (int mj = 0; mj < 16; mj++) {
        float lo, hi;
        unpack2(acc[mj], lo, hi);
        yk[(size_t)(m0 + 2*mj    )*DD + c] = lo;
        yk[(size_t)(m0 + 2*mj + 1)*DD + c] = hi;
        s += lo + hi;
        qv += lo*lo + hi*hi;
    }
    atomicAdd(&g_ysum[k*DD + c], s);
    atomicAdd(&g_ysq[k*DD + c],  qv);
}

// ---------------- K4: y-scale compute + relu(BN(y)) -> 7 head outputs ----------------
__global__ void __launch_bounds__(256) k_out(
                      const float* __restrict__ cew, const float* __restrict__ ceb,
                      const float* __restrict__ lww, const float* __restrict__ lwb,
                      const float* __restrict__ thw, const float* __restrict__ thb,
                      const float* __restrict__ bng, const float* __restrict__ bnb,
                      float* __restrict__ out) {
    __shared__ float ysc[3*DD], ysh[3*DD];
    int tid = threadIdx.x;
    for (int v = tid; v < 3*DD; v += 256) {
        int c = v & 127;
        float inv = 1.0f / (float)MM;
        float mean = g_ysum[v] * inv;
        float var  = g_ysq[v] * inv - mean*mean;
        float sc = bng[c] * rsqrtf(var + EPSV);
        ysc[v] = sc;
        ysh[v] = bnb[c] - mean * sc;
    }
    __syncthreads();

    int gw   = (blockIdx.x * blockDim.x + tid) >> 5;
    int lane = tid & 31;
    int o = lane * 4;
    float r0, r1, r2, r3, r4, r5, r6;
    {
        float4 y = *(const float4*)(g_y0 + (size_t)gw*DD + o);
        float x0 = fmaxf(0.f, fmaf(ysc[0*DD+o+0], y.x, ysh[0*DD+o+0]));
        float x1 = fmaxf(0.f, fmaf(ysc[0*DD+o+1], y.y, ysh[0*DD+o+1]));
        float x2 = fmaxf(0.f, fmaf(ysc[0*DD+o+2], y.z, ysh[0*DD+o+2]));
        float x3 = fmaxf(0.f, fmaf(ysc[0*DD+o+3], y.w, ysh[0*DD+o+3]));
        float4 w0 = *(const float4*)(cew + 0*DD + o);
        float4 w1 = *(const float4*)(cew + 1*DD + o);
        float4 w2 = *(const float4*)(cew + 2*DD + o);
        r0 = x0*w0.x + x1*w0.y + x2*w0.z + x3*w0.w;
        r1 = x0*w1.x + x1*w1.y + x2*w1.z + x3*w1.w;
        r2 = x0*w2.x + x1*w2.y + x2*w2.z + x3*w2.w;
    }
    {
        float4 y = *(const float4*)(g_y1 + (size_t)gw*DD + o);
        float x0 = fmaxf(0.f, fmaf(ysc[1*DD+o+0], y.x, ysh[1*DD+o+0]));
        float x1 = fmaxf(0.f, fmaf(ysc[1*DD+o+1], y.y, ysh[1*DD+o+1]));
        float x2 = fmaxf(0.f, fmaf(ysc[1*DD+o+2], y.z, ysh[1*DD+o+2]));
        float x3 = fmaxf(0.f, fmaf(ysc[1*DD+o+3], y.w, ysh[1*DD+o+3]));
        float4 w0 = *(const float4*)(lww + 0*DD + o);
        float4 w1 = *(const float4*)(lww + 1*DD + o);
        float4 w2 = *(const float4*)(lww + 2*DD + o);
        r3 = x0*w0.x + x1*w0.y + x2*w0.z + x3*w0.w;
        r4 = x0*w1.x + x1*w1.y + x2*w1.z + x3*w1.w;
        r5 = x0*w2.x + x1*w2.y + x2*w2.z + x3*w2.w;
    }
    {
        float4 y = *(const float4*)(g_y2 + (size_t)gw*DD + o);
        float x0 = fmaxf(0.f, fmaf(ysc[2*DD+o+0], y.x, ysh[2*DD+o+0]));
        float x1 = fmaxf(0.f, fmaf(ysc[2*DD+o+1], y.y, ysh[2*DD+o+1]));
        float x2 = fmaxf(0.f, fmaf(ysc[2*DD+o+2], y.z, ysh[2*DD+o+2]));
        float x3 = fmaxf(0.f, fmaf(ysc[2*DD+o+3], y.w, ysh[2*DD+o+3]));
        float4 w0 = *(const float4*)(thw + o);
        r6 = x0*w0.x + x1*w0.y + x2*w0.z + x3*w0.w;
    }
    #pragma unroll
    for (int off = 16; off; off >>= 1) {
        r0 += __shfl_xor_sync(0xffffffffu, r0, off);
        r1 += __shfl_xor_sync(0xffffffffu, r1, off);
        r2 += __shfl_xor_sync(0xffffffffu, r2, off);
        r3 += __shfl_xor_sync(0xffffffffu, r3, off);
        r4 += __shfl_xor_sync(0xffffffffu, r4, off);
        r5 += __shfl_xor_sync(0xffffffffu, r5, off);
        r6 += __shfl_xor_sync(0xffffffffu, r6, off);
    }
    if (lane == 0) {
        float* op = out + (size_t)gw*7;
        op[0] = r0 + ceb[0];
        op[1] = r1 + ceb[1];
        op[2] = r2 + ceb[2];
        op[3] = r3 + lwb[0];
        op[4] = r4 + lwb[1];
        op[5] = r5 + lwb[2];
        op[6] = r6 + thb[0];
    }
}

// ---------------- launch ----------------
extern "C" void kernel_launch(void* const* d_in, const int* in_sizes, int n_in,
                              void* d_out, int out_size) {
    const float* x        = (const float*)d_in[0];
    const float* conv1_w  = (const float*)d_in[1];
    const float* conv1_b  = (const float*)d_in[2];
    const float* bn_g     = (const float*)d_in[3];
    const float* bn_b     = (const float*)d_in[4];
    const float* fc1_w    = (const float*)d_in[5];
    const float* fc1_b    = (const float*)d_in[6];
    const float* fc_ce_w  = (const float*)d_in[7];
    const float* fc_ce_b  = (const float*)d_in[8];
    const float* fc2_w    = (const float*)d_in[9];
    const float* fc2_b    = (const float*)d_in[10];
    const float* fc_lwh_w = (const float*)d_in[11];
    const float* fc_lwh_b = (const float*)d_in[12];
    const float* fc3_w    = (const float*)d_in[13];
    const float* fc3_b    = (const float*)d_in[14];
    const float* fc_th_w  = (const float*)d_in[15];
    const float* fc_th_b  = (const float*)d_in[16];

    float* out  = (float*)d_out;             // (B,N,7) flattened
    float* feat = out + (size_t)MM * 7;      // (B,N,128) flattened after it

    static bool attr_set = false;
    if (!attr_set) {
        cudaFuncSetAttribute(k_gemm, cudaFuncAttributeMaxDynamicSharedMemorySize,
                             SMEM_FLOATS * (int)sizeof(float));
        attr_set = true;
    }

    k_pack<<<(BB*NSrc + 255)/256, 256>>>(x);
    k_ballconv<<<MM/8, 256>>>(x, conv1_w, conv1_b);
    k_gemm<<<MM/32, 384, SMEM_FLOATS * sizeof(float)>>>(
        fc1_w, fc1_b, fc2_w, fc2_b, fc3_w, fc3_b, bn_g, bn_b, feat);
    k_out<<<MM/8, 256>>>(fc_ce_w, fc_ce_b, fc_lwh_w, fc_lwh_b, fc_th_w, fc_th_b,
                         bn_g, bn_b, out);
}

// round 6
// speedup vs baseline: 2.1178x; 1.0460x over previous
#include <cuda_runtime.h>

#define BB 2
#define TT 5
#define NNq 4096
#define CC 16
#define DD 128
#define NSrc 16384          // (T-1)*N
#define MM (BB*NNq)         // 8192
#define EPSV 1e-5f
#define RAD2 1.0f

// ---------------- scratch (__device__ globals) ----------------
__device__ float4 g_xyzw[BB*NSrc];                 // packed src xyz + |s|^2
__device__ float  g_hmax[(size_t)MM*DD];           // max over s of conv pre-BN (4MB)
__device__ float  g_hmin[(size_t)MM*DD];           // min over s                (4MB)
__device__ float  g_y0[(size_t)MM*DD];             // fc1 out (m,c)
__device__ float  g_y1[(size_t)MM*DD];             // fc2 out
__device__ float  g_y2[(size_t)MM*DD];             // fc3 out
__device__ float  g_csum[DD];
__device__ float  g_csq[DD];
__device__ float  g_ysum[3*DD];
__device__ float  g_ysq[3*DD];

// packed f32x2 fma (sm_100+)
__device__ __forceinline__ unsigned long long ffma2(unsigned long long a,
                                                    unsigned long long b,
                                                    unsigned long long c) {
    unsigned long long d;
    asm("fma.rn.f32x2 %0, %1, %2, %3;" : "=l"(d) : "l"(a), "l"(b), "l"(c));
    return d;
}
__device__ __forceinline__ unsigned long long splat2(float w) {
    unsigned long long r;
    asm("mov.b64 %0, {%1, %1};" : "=l"(r) : "r"(__float_as_uint(w)));
    return r;
}
__device__ __forceinline__ void unpack2(unsigned long long v, float& lo, float& hi) {
    unsigned a, b;
    asm("mov.b64 {%0, %1}, %2;" : "=r"(a), "=r"(b) : "l"(v));
    lo = __uint_as_float(a); hi = __uint_as_float(b);
}

// ---------------- K1: pack source xyz + sumsq, zero accumulators ----------------
__global__ void k_pack(const float* __restrict__ x) {
    int i = blockIdx.x * blockDim.x + threadIdx.x;
    if (i < DD)   { g_csum[i] = 0.f; g_csq[i] = 0.f; }
    if (i < 3*DD) { g_ysum[i] = 0.f; g_ysq[i] = 0.f; }
    if (i >= BB*NSrc) return;
    int b = i / NSrc, j = i % NSrc;
    int t = 1 + j / NNq, n = j % NNq;
    const float* p = x + (((size_t)b*TT + t)*NNq + n)*CC;
    float px = p[0], py = p[1], pz = p[2];
    g_xyzw[i] = make_float4(px, py, pz, px*px + py*py + pz*pz);
}

// ---------------- K2: ball query + conv + max/min + BN stats (no shared atomics) ----
__global__ void __launch_bounds__(256) k_ballconv(const float* __restrict__ x,
                           const float* __restrict__ w,
                           const float* __restrict__ bias) {
    __shared__ float sg[8][64];        // per-warp grouped feats [s][c]
    __shared__ float swsum[8][DD];     // per-warp exclusive stat slots
    __shared__ float swsq[8][DD];
    int tid  = threadIdx.x;
    int wrp  = tid >> 5;
    int gw   = (blockIdx.x * blockDim.x + tid) >> 5;
    int lane = tid & 31;

    int b = gw >> 12, q = gw & (NNq - 1);

    const float* qp = x + (((size_t)b*TT + 0)*NNq + q)*CC;
    float qx = qp[0], qy = qp[1], qz = qp[2];
    float qq = qx*qx + qy*qy + qz*qz;

    const float4* src = g_xyzw + (size_t)b*NSrc;
    int i0 = 0, i1 = 0, i2 = 0, i3 = 0, cnt = 0;

    // pipelined scan: 256 points per super-chunk (8 x float4 per lane), prefetch next
    const int NCH = NSrc / 256;   // 64
    float4 P[8];
    #pragma unroll
    for (int j = 0; j < 8; j++) P[j] = src[j*32 + lane];
    for (int sc = 0; sc < NCH && cnt < 4; sc++) {
        float4 C[8];
        #pragma unroll
        for (int j = 0; j < 8; j++) C[j] = P[j];
        int nxt = (sc + 1 < NCH) ? sc + 1 : sc;
        #pragma unroll
        for (int j = 0; j < 8; j++) P[j] = src[nxt*256 + j*32 + lane];
        #pragma unroll
        for (int j = 0; j < 8; j++) {
            float dot = fmaf(qx, C[j].x, fmaf(qy, C[j].y, qz*C[j].z));
            float d2  = fmaf(-2.0f, dot, qq + C[j].w);
            unsigned mask = __ballot_sync(0xffffffffu, d2 < RAD2);
            while (mask && cnt < 4) {
                int id = sc*256 + j*32 + (__ffs(mask) - 1);
                if      (cnt == 0) i0 = id;
                else if (cnt == 1) i1 = id;
                else if (cnt == 2) i2 = id;
                else               i3 = id;
                cnt++;
                mask &= mask - 1;
            }
        }
    }
    bool empty = (cnt == 0);
    if (cnt < 2) i1 = i0;
    if (cnt < 3) i2 = i0;
    if (cnt < 4) i3 = i0;

    // gather grouped feats into shared  (g[s][c])
    float* gg = &sg[wrp][0];
    const float* feats = x + ((size_t)b*TT + 1)*NNq*CC;
    #pragma unroll
    for (int r = 0; r < 2; r++) {
        int v = lane + r*32;          // v = s*16 + c
        int s = v >> 4, c = v & 15;
        int id = (s == 0) ? i0 : (s == 1) ? i1 : (s == 2) ? i2 : i3;
        gg[v] = empty ? 0.0f : feats[(size_t)id*CC + c];
    }
    __syncwarp();

    // conv: h[m,o,s] = sum_c g[s][c]*w[o,c] + b[o]; keep max/min; per-warp stats
    float* hmaxr = g_hmax + (size_t)gw * DD;
    float* hminr = g_hmin + (size_t)gw * DD;
    #pragma unroll
    for (int j = 0; j < 4; j++) {
        int o = lane + j*32;
        float bo = bias[o];
        float a0 = bo, a1 = bo, a2 = bo, a3 = bo;
        const float* wr = w + o*CC;
        #pragma unroll
        for (int c = 0; c < CC; c++) {
            float wv = wr[c];
            a0 = fmaf(wv, gg[0*16 + c], a0);
            a1 = fmaf(wv, gg[1*16 + c], a1);
            a2 = fmaf(wv, gg[2*16 + c], a2);
            a3 = fmaf(wv, gg[3*16 + c], a3);
        }
        float mx = fmaxf(fmaxf(a0, a1), fmaxf(a2, a3));
        float mn = fminf(fminf(a0, a1), fminf(a2, a3));
        hmaxr[o] = mx;
        hminr[o] = mn;
        swsum[wrp][o] = a0 + a1 + a2 + a3;
        swsq[wrp][o]  = a0*a0 + a1*a1 + a2*a2 + a3*a3;
    }
    __syncthreads();
    if (tid < DD) {
        float s = 0.f, qv = 0.f;
        #pragma unroll
        for (int u = 0; u < 8; u++) { s += swsum[u][tid]; qv += swsq[u][tid]; }
        atomicAdd(&g_csum[tid], s);
        atomicAdd(&g_csq[tid],  qv);
    }
}

// ---------------- K3: scale + BN+maxpool + fused GEMM (m-tile 64) + y-stats ---------
#define MTILE 64
#define SH_OFF 256
#define SH_PITCH 68
#define SW_OFF (SH_OFF + DD*SH_PITCH)
#define SW_PITCH 36
#define SMEM_FLOATS (SW_OFF + 3*DD*SW_PITCH)

__global__ void __launch_bounds__(384) k_gemm(
        const float* __restrict__ fc1w, const float* __restrict__ fc1b,
        const float* __restrict__ fc2w, const float* __restrict__ fc2b,
        const float* __restrict__ fc3w, const float* __restrict__ fc3b,
        const float* __restrict__ bng,  const float* __restrict__ bnb,
        float* __restrict__ feat_out) {
    extern __shared__ float sm[];
    float* sscale = sm;
    float* sshift = sm + DD;
    float* sh     = sm + SH_OFF;
    float* sw     = sm + SW_OFF;
    int tid = threadIdx.x;
    int m0 = blockIdx.x * MTILE;

    if (tid < DD) {
        float inv = 1.0f / (float)(MM*4);
        float mean = g_csum[tid] * inv;
        float var  = g_csq[tid] * inv - mean*mean;
        float sc = bng[tid] * rsqrtf(var + EPSV);
        sscale[tid] = sc;
        sshift[tid] = bnb[tid] - mean * sc;
    }
    __syncthreads();

    // BN + maxpool from (hmax,hmin) -> sh transposed + feature output
    for (int v = tid; v < MTILE*DD; v += 384) {
        int mi = v >> 7, o = v & 127;
        float hx = g_hmax[(size_t)(m0+mi)*DD + o];
        float hn = g_hmin[(size_t)(m0+mi)*DD + o];
        float sc = sscale[o], sf = sshift[o];
        float hv = fmaxf(fmaf(sc, hx, sf), fmaf(sc, hn, sf));
        sh[o*SH_PITCH + mi] = hv;
        feat_out[(size_t)(m0+mi)*DD + o] = hv;
    }

    int k = tid >> 7;
    int c = tid & 127;
    float bb = ((k == 0) ? fc1b : (k == 1) ? fc2b : fc3b)[c];
    unsigned long long acc[32];
    unsigned long long b2 = splat2(bb);
    #pragma unroll
    for (int mj = 0; mj < 32; mj++) acc[mj] = b2;

    for (int oc = 0; oc < 4; oc++) {
        __syncthreads();
        for (int v = tid; v < 3*DD*32; v += 384) {
            int kk = v >> 12, rest = v & 4095;
            int cc = rest >> 5, oi = rest & 31;
            const float* Ws = (kk == 0) ? fc1w : (kk == 1) ? fc2w : fc3w;
            sw[(kk*DD + cc)*SW_PITCH + oi] = Ws[(size_t)cc*DD + oc*32 + oi];
        }
        __syncthreads();
        const float* wr = &sw[(k*DD + c)*SW_PITCH];
        #pragma unroll
        for (int oi = 0; oi < 32; oi += 4) {
            float4 w4 = *(const float4*)(wr + oi);
            #pragma unroll
            for (int u = 0; u < 4; u++) {
                float wv = (u == 0) ? w4.x : (u == 1) ? w4.y : (u == 2) ? w4.z : w4.w;
                unsigned long long w2 = splat2(wv);
                int o = oc*32 + oi + u;
                const ulonglong2* hb =
                    reinterpret_cast<const ulonglong2*>(&sh[o*SH_PITCH]);
                #pragma unroll
                for (int mj = 0; mj < 16; mj++) {
                    ulonglong2 h2 = hb[mj];
                    acc[2*mj    ] = ffma2(w2, h2.x, acc[2*mj    ]);
                    acc[2*mj + 1] = ffma2(w2, h2.y, acc[2*mj + 1]);
                }
            }
        }
    }

    float* yk = (k == 0) ? g_y0 : (k == 1) ? g_y1 : g_y2;
    float s = 0.f, qv = 0.f;
    #pragma unroll
    for (int mj = 0; mj < 32; mj++) {
        float lo, hi;
        unpack2(acc[mj], lo, hi);
        yk[(size_t)(m0 + 2*mj    )*DD + c] = lo;
        yk[(size_t)(m0 + 2*mj + 1)*DD + c] = hi;
        s += lo + hi;
        qv += lo*lo + hi*hi;
    }
    atomicAdd(&g_ysum[k*DD + c], s);
    atomicAdd(&g_ysq[k*DD + c],  qv);
}

// ---------------- K4: y-scale + relu(BN(y)) -> 7 head outputs (4 m per warp) --------
__global__ void __launch_bounds__(256) k_out(
                      const float* __restrict__ cew, const float* __restrict__ ceb,
                      const float* __restrict__ lww, const float* __restrict__ lwb,
                      const float* __restrict__ thw, const float* __restrict__ thb,
                      const float* __restrict__ bng, const float* __restrict__ bnb,
                      float* __restrict__ out) {
    __shared__ float ysc[3*DD], ysh[3*DD];
    int tid = threadIdx.x;
    for (int v = tid; v < 3*DD; v += 256) {
        int c = v & 127;
        float inv = 1.0f / (float)MM;
        float mean = g_ysum[v] * inv;
        float var  = g_ysq[v] * inv - mean*mean;
        float sc = bng[c] * rsqrtf(var + EPSV);
        ysc[v] = sc;
        ysh[v] = bnb[c] - mean * sc;
    }
    __syncthreads();

    int warp = (blockIdx.x * blockDim.x + tid) >> 5;
    int lane = tid & 31;
    int gwb  = warp * 4;                 // 4 queries per warp
    int o = lane * 4;

    float4 y0[4], y1[4], y2[4];
    #pragma unroll
    for (int km = 0; km < 4; km++) {
        y0[km] = *(const float4*)(g_y0 + (size_t)(gwb+km)*DD + o);
        y1[km] = *(const float4*)(g_y1 + (size_t)(gwb+km)*DD + o);
        y2[km] = *(const float4*)(g_y2 + (size_t)(gwb+km)*DD + o);
    }
    float4 wce0 = *(const float4*)(cew + 0*DD + o);
    float4 wce1 = *(const float4*)(cew + 1*DD + o);
    float4 wce2 = *(const float4*)(cew + 2*DD + o);
    float4 wlw0 = *(const float4*)(lww + 0*DD + o);
    float4 wlw1 = *(const float4*)(lww + 1*DD + o);
    float4 wlw2 = *(const float4*)(lww + 2*DD + o);
    float4 wth  = *(const float4*)(thw + o);

    float r[7][4];
    #pragma unroll
    for (int km = 0; km < 4; km++) {
        {
            float x0 = fmaxf(0.f, fmaf(ysc[0*DD+o+0], y0[km].x, ysh[0*DD+o+0]));
            float x1 = fmaxf(0.f, fmaf(ysc[0*DD+o+1], y0[km].y, ysh[0*DD+o+1]));
            float x2 = fmaxf(0.f, fmaf(ysc[0*DD+o+2], y0[km].z, ysh[0*DD+o+2]));
            float x3 = fmaxf(0.f, fmaf(ysc[0*DD+o+3], y0[km].w, ysh[0*DD+o+3]));
            r[0][km] = x0*wce0.x + x1*wce0.y + x2*wce0.z + x3*wce0.w;
            r[1][km] = x0*wce1.x + x1*wce1.y + x2*wce1.z + x3*wce1.w;
            r[2][km] = x0*wce2.x + x1*wce2.y + x2*wce2.z + x3*wce2.w;
        }
        {
            float x0 = fmaxf(0.f, fmaf(ysc[1*DD+o+0], y1[km].x, ysh[1*DD+o+0]));
            float x1 = fmaxf(0.f, fmaf(ysc[1*DD+o+1], y1[km].y, ysh[1*DD+o+1]));
            float x2 = fmaxf(0.f, fmaf(ysc[1*DD+o+2], y1[km].z, ysh[1*DD+o+2]));
            float x3 = fmaxf(0.f, fmaf(ysc[1*DD+o+3], y1[km].w, ysh[1*DD+o+3]));
            r[3][km] = x0*wlw0.x + x1*wlw0.y + x2*wlw0.z + x3*wlw0.w;
            r[4][km] = x0*wlw1.x + x1*wlw1.y + x2*wlw1.z + x3*wlw1.w;
            r[5][km] = x0*wlw2.x + x1*wlw2.y + x2*wlw2.z + x3*wlw2.w;
        }
        {
            float x0 = fmaxf(0.f, fmaf(ysc[2*DD+o+0], y2[km].x, ysh[2*DD+o+0]));
            float x1 = fmaxf(0.f, fmaf(ysc[2*DD+o+1], y2[km].y, ysh[2*DD+o+1]));
            float x2 = fmaxf(0.f, fmaf(ysc[2*DD+o+2], y2[km].z, ysh[2*DD+o+2]));
            float x3 = fmaxf(0.f, fmaf(ysc[2*DD+o+3], y2[km].w, ysh[2*DD+o+3]));
            r[6][km] = x0*wth.x + x1*wth.y + x2*wth.z + x3*wth.w;
        }
    }
    #pragma unroll
    for (int h = 0; h < 7; h++)
        #pragma unroll
        for (int km = 0; km < 4; km++)
            #pragma unroll
            for (int off = 16; off; off >>= 1)
                r[h][km] += __shfl_xor_sync(0xffffffffu, r[h][km], off);

    if (lane == 0) {
        #pragma unroll
        for (int km = 0; km < 4; km++) {
            float* op = out + (size_t)(gwb + km)*7;
            op[0] = r[0][km] + ceb[0];
            op[1] = r[1][km] + ceb[1];
            op[2] = r[2][km] + ceb[2];
            op[3] = r[3][km] + lwb[0];
            op[4] = r[4][km] + lwb[1];
            op[5] = r[5][km] + lwb[2];
            op[6] = r[6][km] + thb[0];
        }
    }
}

// ---------------- launch ----------------
extern "C" void kernel_launch(void* const* d_in, const int* in_sizes, int n_in,
                              void* d_out, int out_size) {
    const float* x        = (const float*)d_in[0];
    const float* conv1_w  = (const float*)d_in[1];
    const float* conv1_b  = (const float*)d_in[2];
    const float* bn_g     = (const float*)d_in[3];
    const float* bn_b     = (const float*)d_in[4];
    const float* fc1_w    = (const float*)d_in[5];
    const float* fc1_b    = (const float*)d_in[6];
    const float* fc_ce_w  = (const float*)d_in[7];
    const float* fc_ce_b  = (const float*)d_in[8];
    const float* fc2_w    = (const float*)d_in[9];
    const float* fc2_b    = (const float*)d_in[10];
    const float* fc_lwh_w = (const float*)d_in[11];
    const float* fc_lwh_b = (const float*)d_in[12];
    const float* fc3_w    = (const float*)d_in[13];
    const float* fc3_b    = (const float*)d_in[14];
    const float* fc_th_w  = (const float*)d_in[15];
    const float* fc_th_b  = (const float*)d_in[16];

    float* out  = (float*)d_out;             // (B,N,7) flattened
    float* feat = out + (size_t)MM * 7;      // (B,N,128) flattened after it

    static bool attr_set = false;
    if (!attr_set) {
        cudaFuncSetAttribute(k_gemm, cudaFuncAttributeMaxDynamicSharedMemorySize,
                             SMEM_FLOATS * (int)sizeof(float));
        attr_set = true;
    }

    k_pack<<<(BB*NSrc + 255)/256, 256>>>(x);
    k_ballconv<<<MM/8, 256>>>(x, conv1_w, conv1_b);
    k_gemm<<<MM/MTILE, 384, SMEM_FLOATS * sizeof(float)>>>(
        fc1_w, fc1_b, fc2_w, fc2_b, fc3_w, fc3_b, bn_g, bn_b, feat);
    k_out<<<MM/32, 256>>>(fc_ce_w, fc_ce_b, fc_lwh_w, fc_lwh_b, fc_th_w, fc_th_b,
                          bn_g, bn_b, out);
}